// round 9
// baseline (speedup 1.0000x reference)
#include <cuda_runtime.h>
#include <cuda_fp16.h>

// Trilinear 3D grid sample, (y,z,c)-fused fp16 corner layout.
// im:      [B, X, Y, Z, C] float32, B=2, X=Y=Z=160, C=2
// defgrid: [B, X, Y, Z, 3] float32
// out:     [B, X, Y, Z, C] float32
//
// P2[b][x][y][z] = 8 halves (16B): {(y,z),(y,z+1),(y+1,z),(y+1,z+1)} x {c0,c1}.
// Each voxel: TWO divergent 16B gathers (one per x-corner).
// Gather processes 4 voxels/thread: 8 gathers issued up-front for MLP to
// hide table L2-miss latency. Streaming uses evict-first (.cs).
// Sequential schedule: pre(0) -> gather(0) -> pre(1) -> gather(1).

#define XD 160
#define YD 160
#define ZD 160
#define BD 2
#define VOL (XD * YD * ZD)          // 4,096,000
#define THREADS 256
#define PRE_BLOCKS (VOL / 2 / THREADS)      // 8000 (2 voxels/thread)
#define GATHER_BLOCKS (VOL / 4 / THREADS)   // 4000 (4 voxels/thread)

__device__ uint4 g_P2[BD][VOL];

__device__ __forceinline__ unsigned int pack_h2(float a, float b) {
    __half2 h = __floats2half2_rn(a, b);
    return *(unsigned int*)&h;
}

// ---------- preprocess: 2 consecutive-z voxels per thread ----------
__global__ __launch_bounds__(THREADS) void preprocess_kernel(
    const float2* __restrict__ im, int b)
{
    int t = blockIdx.x * THREADS + threadIdx.x;
    if (t >= VOL / 2) return;

    int i = t * 2;              // even; ZD=160 even => pair stays in one z-row
    int z = i % ZD;             // even, 0..158
    int y = (i / ZD) % YD;

    const float2* __restrict__ imb = im + (size_t)b * VOL;
    int yp = (y < YD - 1) ? ZD : 0;   // clamp y+1
    int j  = i + yp;

    float4 a4 = __ldcs((const float4*)(imb + i));
    float2 c  = (z + 2 < ZD) ? __ldcs(&imb[i + 2]) : make_float2(a4.z, a4.w);
    float4 b4 = __ldcs((const float4*)(imb + j));
    float2 d  = (z + 2 < ZD) ? __ldcs(&imb[j + 2]) : make_float2(b4.z, b4.w);

    uint4 p0, p1;
    p0.x = pack_h2(a4.x, a4.y);   // (y  , z  )
    p0.y = pack_h2(a4.z, a4.w);   // (y  , z+1)
    p0.z = pack_h2(b4.x, b4.y);   // (y+1, z  )
    p0.w = pack_h2(b4.z, b4.w);   // (y+1, z+1)

    p1.x = p0.y;                  // (y  , z+1)
    p1.y = pack_h2(c.x, c.y);     // (y  , z+2 clamped)
    p1.z = p0.w;                  // (y+1, z+1)
    p1.w = pack_h2(d.x, d.y);     // (y+1, z+2 clamped)

    g_P2[b][i]     = p0;
    g_P2[b][i + 1] = p1;
}

__device__ __forceinline__ float2 h2f(unsigned int u) {
    __half2 h = *(__half2*)&u;
    return __half22float2(h);
}

__device__ __forceinline__ float2 interp_voxel(
    float x, float y, float z, uint4 q0, uint4 q1,
    int x0, int y0u, int z0u, int zc)
{
    // Lower-edge clip duplication (coords >= 0 so ~never taken; keeps exact
    // reference semantics).
    if (z0u < 0) { q0.y = q0.x; q0.w = q0.z; q1.y = q1.x; q1.w = q1.z; }
    if (y0u < 0) { q0.z = q0.x; q0.w = q0.y; q1.z = q1.x; q1.w = q1.y; }

    float2 Ia = h2f(q0.x), Ib = h2f(q0.y), Ic = h2f(q0.z), Id = h2f(q0.w);
    float2 Ie = h2f(q1.x), If = h2f(q1.y), Ig = h2f(q1.z), Ih = h2f(q1.w);

    int y0 = min(max(y0u, 0), YD - 1);
    const float xd = x - (float)x0;
    const float yd = y - (float)y0;
    const float zd = z - (float)zc;
    const float xm = 1.0f - xd;
    const float ym = 1.0f - yd;
    const float zm = 1.0f - zd;

    float cae0 = Ia.x * xm + Ie.x * xd;
    float cae1 = Ia.y * xm + Ie.y * xd;
    float cbf0 = Ib.x * xm + If.x * xd;
    float cbf1 = Ib.y * xm + If.y * xd;
    float ccg0 = Ic.x * xm + Ig.x * xd;
    float ccg1 = Ic.y * xm + Ig.y * xd;
    float cdh0 = Id.x * xm + Ih.x * xd;
    float cdh1 = Id.y * xm + Ih.y * xd;

    float c0_0 = cae0 * ym + ccg0 * yd;
    float c0_1 = cae1 * ym + ccg1 * yd;
    float c1_0 = cbf0 * ym + cdh0 * yd;
    float c1_1 = cbf1 * ym + cdh1 * yd;

    float2 r;
    r.x = c0_0 * zm + c1_0 * zd;
    r.y = c0_1 * zm + c1_1 * zd;
    return r;
}

// ---------- gather: 4 voxels per thread, 8 gathers in flight ----------
__global__ __launch_bounds__(THREADS, 4) void gather_kernel(
    const float* __restrict__ defgrid,
    float4* __restrict__ out, int b)
{
    int t = blockIdx.x * THREADS + threadIdx.x;
    if (t >= VOL / 4) return;

    int i  = t * 4;
    int gi = b * VOL + i;

    // coords for 4 voxels: 12 floats = 3 coalesced float4 (48B, 16B-aligned)
    const float4* dg = (const float4*)(defgrid + (size_t)3 * gi);
    float4 v0 = __ldcs(dg + 0);   // x0 y0 z0 x1
    float4 v1 = __ldcs(dg + 1);   // y1 z1 x2 y2
    float4 v2 = __ldcs(dg + 2);   // z2 x3 y3 z3

    float cx[4] = { v0.x, v0.w, v1.z, v2.y };
    float cy[4] = { v0.y, v1.x, v1.w, v2.z };
    float cz[4] = { v0.z, v1.y, v2.x, v2.w };

    int x0a[4], x1a[4], y0u[4], z0u[4], zc[4];
#pragma unroll
    for (int k = 0; k < 4; k++) {
        int xf = (int)floorf(cx[k]);
        int yf = (int)floorf(cy[k]);
        int zf = (int)floorf(cz[k]);
        x0a[k] = min(max(xf, 0), XD - 1);
        x1a[k] = min(max(xf + 1, 0), XD - 1);
        y0u[k] = yf;
        z0u[k] = zf;
        zc[k]  = min(max(zf, 0), ZD - 1);
    }

    const uint4* __restrict__ Pb = g_P2[b];

    // Issue all 8 gathers before consuming any (MLP).
    uint4 q0[4], q1[4];
#pragma unroll
    for (int k = 0; k < 4; k++) {
        int yc = min(max(y0u[k], 0), YD - 1);
        int r0 = (x0a[k] * YD + yc) * ZD + zc[k];
        int r1 = (x1a[k] * YD + yc) * ZD + zc[k];
        q0[k] = __ldg(&Pb[r0]);
        q1[k] = __ldg(&Pb[r1]);
    }

    float2 r0 = interp_voxel(cx[0], cy[0], cz[0], q0[0], q1[0], x0a[0], y0u[0], z0u[0], zc[0]);
    float2 r1 = interp_voxel(cx[1], cy[1], cz[1], q0[1], q1[1], x0a[1], y0u[1], z0u[1], zc[1]);
    float2 r2 = interp_voxel(cx[2], cy[2], cz[2], q0[2], q1[2], x0a[2], y0u[2], z0u[2], zc[2]);
    float2 r3 = interp_voxel(cx[3], cy[3], cz[3], q0[3], q1[3], x0a[3], y0u[3], z0u[3], zc[3]);

    int o = gi / 2;               // float4 index (2 voxels per float4)
    __stcs(&out[o + 0], make_float4(r0.x, r0.y, r1.x, r1.y));
    __stcs(&out[o + 1], make_float4(r2.x, r2.y, r3.x, r3.y));
}

extern "C" void kernel_launch(void* const* d_in, const int* in_sizes, int n_in,
                              void* d_out, int out_size)
{
    const float2* im     = (const float2*)d_in[0];
    const float* defgrid = (const float*)d_in[1];
    float4* out          = (float4*)d_out;

    for (int b = 0; b < BD; b++) {
        preprocess_kernel<<<PRE_BLOCKS, THREADS>>>(im, b);
        gather_kernel<<<GATHER_BLOCKS, THREADS>>>(defgrid, out, b);
    }
}

// round 11
// speedup vs baseline: 1.5168x; 1.5168x over previous
#include <cuda_runtime.h>
#include <cuda_fp16.h>

// Trilinear 3D grid sample, (y,z,c)-fused fp16 corner layout.
// im:      [B, X, Y, Z, C] float32, B=2, X=Y=Z=160, C=2
// defgrid: [B, X, Y, Z, 3] float32
// out:     [B, X, Y, Z, C] float32
//
// P2[b][x][y][z] = 8 halves (16B): {(y,z),(y,z+1),(y+1,z),(y+1,z+1)} x {c0,c1}.
// Gather: TWO divergent 16B gathers per voxel (the structural minimum),
// 2 voxels/thread, 32 regs, ~88% occupancy.
// Schedule: pre0(keep-resident writes) -> [gather0 || pre1(evict-first
// writes, so table0 keeps its L2 residency)] -> gather1.

#define XD 160
#define YD 160
#define ZD 160
#define BD 2
#define VOL (XD * YD * ZD)          // 4,096,000
#define THREADS 256
#define PRE_BLOCKS (VOL / 2 / THREADS)      // 8000 (2 voxels/thread)
#define GATHER_BLOCKS (VOL / 2 / THREADS)   // 8000 (2 voxels/thread)

__device__ uint4 g_P2[BD][VOL];

__device__ __forceinline__ unsigned int pack_h2(float a, float b) {
    __half2 h = __floats2half2_rn(a, b);
    return *(unsigned int*)&h;
}

// ---------- preprocess body: 2 consecutive-z voxels per thread ----------
// STREAM_STORES=true writes the table evict-first (.cs) so it does not evict
// the other batch's table during the fused phase.
template <bool STREAM_STORES>
__device__ __forceinline__ void preprocess_body(
    const float2* __restrict__ im, int b, int t)
{
    if (t >= VOL / 2) return;

    int i = t * 2;              // even; ZD=160 even => pair stays in one z-row
    int z = i % ZD;             // even, 0..158
    int y = (i / ZD) % YD;

    const float2* __restrict__ imb = im + (size_t)b * VOL;
    int yp = (y < YD - 1) ? ZD : 0;   // clamp y+1
    int j  = i + yp;

    float4 a4 = __ldcs((const float4*)(imb + i));
    float2 c  = (z + 2 < ZD) ? __ldcs(&imb[i + 2]) : make_float2(a4.z, a4.w);
    float4 b4 = __ldcs((const float4*)(imb + j));
    float2 d  = (z + 2 < ZD) ? __ldcs(&imb[j + 2]) : make_float2(b4.z, b4.w);

    uint4 p0, p1;
    p0.x = pack_h2(a4.x, a4.y);   // (y  , z  )
    p0.y = pack_h2(a4.z, a4.w);   // (y  , z+1)
    p0.z = pack_h2(b4.x, b4.y);   // (y+1, z  )
    p0.w = pack_h2(b4.z, b4.w);   // (y+1, z+1)

    p1.x = p0.y;                  // (y  , z+1)
    p1.y = pack_h2(c.x, c.y);     // (y  , z+2 clamped)
    p1.z = p0.w;                  // (y+1, z+1)
    p1.w = pack_h2(d.x, d.y);     // (y+1, z+2 clamped)

    if (STREAM_STORES) {
        __stcs(&g_P2[b][i],     p0);
        __stcs(&g_P2[b][i + 1], p1);
    } else {
        g_P2[b][i]     = p0;
        g_P2[b][i + 1] = p1;
    }
}

__device__ __forceinline__ float2 h2f(unsigned int u) {
    __half2 h = *(__half2*)&u;
    return __half22float2(h);
}

__device__ __forceinline__ float2 interp_voxel(
    float x, float y, float z, uint4 q0, uint4 q1,
    int x0, int y0u, int z0u, int zc)
{
    // Lower-edge clip duplication (coords >= 0 so ~never taken; keeps exact
    // reference semantics).
    if (z0u < 0) { q0.y = q0.x; q0.w = q0.z; q1.y = q1.x; q1.w = q1.z; }
    if (y0u < 0) { q0.z = q0.x; q0.w = q0.y; q1.z = q1.x; q1.w = q1.y; }

    float2 Ia = h2f(q0.x), Ib = h2f(q0.y), Ic = h2f(q0.z), Id = h2f(q0.w);
    float2 Ie = h2f(q1.x), If = h2f(q1.y), Ig = h2f(q1.z), Ih = h2f(q1.w);

    int y0 = min(max(y0u, 0), YD - 1);
    const float xd = x - (float)x0;
    const float yd = y - (float)y0;
    const float zd = z - (float)zc;
    const float xm = 1.0f - xd;
    const float ym = 1.0f - yd;
    const float zm = 1.0f - zd;

    float cae0 = Ia.x * xm + Ie.x * xd;
    float cae1 = Ia.y * xm + Ie.y * xd;
    float cbf0 = Ib.x * xm + If.x * xd;
    float cbf1 = Ib.y * xm + If.y * xd;
    float ccg0 = Ic.x * xm + Ig.x * xd;
    float ccg1 = Ic.y * xm + Ig.y * xd;
    float cdh0 = Id.x * xm + Ih.x * xd;
    float cdh1 = Id.y * xm + Ih.y * xd;

    float c0_0 = cae0 * ym + ccg0 * yd;
    float c0_1 = cae1 * ym + ccg1 * yd;
    float c1_0 = cbf0 * ym + cdh0 * yd;
    float c1_1 = cbf1 * ym + cdh1 * yd;

    float2 r;
    r.x = c0_0 * zm + c1_0 * zd;
    r.y = c0_1 * zm + c1_1 * zd;
    return r;
}

// ---------- gather body: one voxel-pair per thread ----------
__device__ __forceinline__ void gather_body(
    const float* __restrict__ defgrid,
    float4* __restrict__ out, int b, int t)
{
    if (t >= VOL / 2) return;

    int i  = t * 2;
    int gi = b * VOL + i;

    const float2* dg = (const float2*)(defgrid + (size_t)3 * gi);
    float2 d0 = __ldcs(dg + 0);   // xA, yA
    float2 d1 = __ldcs(dg + 1);   // zA, xB
    float2 d2 = __ldcs(dg + 2);   // yB, zB

    const float xA = d0.x, yA = d0.y, zA = d1.x;
    const float xB = d1.y, yB = d2.x, zB = d2.y;

    int xA0u = (int)floorf(xA), yA0u = (int)floorf(yA), zA0u = (int)floorf(zA);
    int xA0 = min(max(xA0u, 0), XD - 1);
    int xA1 = min(max(xA0u + 1, 0), XD - 1);
    int yA0 = min(max(yA0u, 0), YD - 1);
    int zAc = min(max(zA0u, 0), ZD - 1);

    int xB0u = (int)floorf(xB), yB0u = (int)floorf(yB), zB0u = (int)floorf(zB);
    int xB0 = min(max(xB0u, 0), XD - 1);
    int xB1 = min(max(xB0u + 1, 0), XD - 1);
    int yB0 = min(max(yB0u, 0), YD - 1);
    int zBc = min(max(zB0u, 0), ZD - 1);

    const uint4* __restrict__ Pb = g_P2[b];

    uint4 qA0 = __ldg(&Pb[(xA0 * YD + yA0) * ZD + zAc]);
    uint4 qA1 = __ldg(&Pb[(xA1 * YD + yA0) * ZD + zAc]);
    uint4 qB0 = __ldg(&Pb[(xB0 * YD + yB0) * ZD + zBc]);
    uint4 qB1 = __ldg(&Pb[(xB1 * YD + yB0) * ZD + zBc]);

    float2 rA = interp_voxel(xA, yA, zA, qA0, qA1, xA0, yA0u, zA0u, zAc);
    float2 rB = interp_voxel(xB, yB, zB, qB0, qB1, xB0, yB0u, zB0u, zBc);

    float4 o = make_float4(rA.x, rA.y, rB.x, rB.y);
    __stcs(&out[gi / 2], o);
}

// ---------- kernels ----------
__global__ __launch_bounds__(THREADS) void preprocess_kernel(
    const float2* __restrict__ im, int b)
{
    int t = blockIdx.x * THREADS + threadIdx.x;
    preprocess_body<false>(im, b, t);
}

__global__ __launch_bounds__(THREADS) void gather_kernel(
    const float* __restrict__ defgrid,
    float4* __restrict__ out, int b)
{
    int t = blockIdx.x * THREADS + threadIdx.x;
    gather_body(defgrid, out, b, t);
}

// Fused: gather(b=0) on even blocks, preprocess(b=1) on odd blocks.
// pre1 writes its table evict-first so table0 keeps L2 residency while
// gather0 reads it; table1 is DRAM-backed (gather already refetches more
// than one full table from DRAM, so gather1 pays ~nothing extra).
__global__ __launch_bounds__(THREADS) void fused_kernel(
    const float2* __restrict__ im,
    const float* __restrict__ defgrid,
    float4* __restrict__ out)
{
    int bx = blockIdx.x;            // 0 .. 2*GATHER_BLOCKS-1 (= 16000)
    int k  = bx >> 1;
    if ((bx & 1) == 0) {
        int t = k * THREADS + threadIdx.x;
        gather_body(defgrid, out, 0, t);
    } else {
        int t = k * THREADS + threadIdx.x;
        preprocess_body<true>(im, 1, t);
    }
}

extern "C" void kernel_launch(void* const* d_in, const int* in_sizes, int n_in,
                              void* d_out, int out_size)
{
    const float2* im     = (const float2*)d_in[0];
    const float* defgrid = (const float*)d_in[1];
    float4* out          = (float4*)d_out;

    preprocess_kernel<<<PRE_BLOCKS, THREADS>>>(im, 0);
    fused_kernel<<<2 * GATHER_BLOCKS, THREADS>>>(im, defgrid, out);
    gather_kernel<<<GATHER_BLOCKS, THREADS>>>(defgrid, out, 1);
}

// round 13
// speedup vs baseline: 1.5429x; 1.0172x over previous
#include <cuda_runtime.h>
#include <cuda_fp16.h>

// Trilinear 3D grid sample, (y,z,c)-fused fp16 corner layout.
// im:      [B, X, Y, Z, C] float32, B=2, X=Y=Z=160, C=2
// defgrid: [B, X, Y, Z, 3] float32
// out:     [B, X, Y, Z, C] float32
//
// P2[x][y][z] = 8 halves (16B): {(y,z),(y,z+1),(y+1,z),(y+1,z+1)} x {c0,c1}.
// ONE table shared by both batches (sequential): batch1's preprocess
// write-hits batch0's resident dirty lines in L2, avoiding the 65MB
// writeback+refetch wave that two disjoint tables cause.
// Gather: 2 voxel-pairs per thread with coord prefetch, so the second
// pair's DRAM coord fetch overlaps the first pair's table-gather latency.

#define XD 160
#define YD 160
#define ZD 160
#define BD 2
#define VOL (XD * YD * ZD)          // 4,096,000
#define THREADS 256
#define PRE_BLOCKS (VOL / 2 / THREADS)      // 8000 (2 voxels/thread)
#define NPAIR (VOL / 2)                     // 2,048,000 voxel-pairs
#define PSTRIDE (NPAIR / 2)                 // 1,024,000 (2 pairs/thread)
#define GATHER_BLOCKS (PSTRIDE / THREADS)   // 4000

__device__ uint4 g_P2[VOL];   // single shared table (scratch, per-batch)

__device__ __forceinline__ unsigned int pack_h2(float a, float b) {
    __half2 h = __floats2half2_rn(a, b);
    return *(unsigned int*)&h;
}

// ---------- preprocess: 2 consecutive-z voxels per thread ----------
__global__ __launch_bounds__(THREADS) void preprocess_kernel(
    const float2* __restrict__ im, int b)
{
    int t = blockIdx.x * THREADS + threadIdx.x;
    if (t >= VOL / 2) return;

    int i = t * 2;              // even; ZD=160 even => pair stays in one z-row
    int z = i % ZD;             // even, 0..158
    int y = (i / ZD) % YD;

    const float2* __restrict__ imb = im + (size_t)b * VOL;
    int yp = (y < YD - 1) ? ZD : 0;   // clamp y+1
    int j  = i + yp;

    float4 a4 = __ldcs((const float4*)(imb + i));
    float2 c  = (z + 2 < ZD) ? __ldcs(&imb[i + 2]) : make_float2(a4.z, a4.w);
    float4 b4 = __ldcs((const float4*)(imb + j));
    float2 d  = (z + 2 < ZD) ? __ldcs(&imb[j + 2]) : make_float2(b4.z, b4.w);

    uint4 p0, p1;
    p0.x = pack_h2(a4.x, a4.y);   // (y  , z  )
    p0.y = pack_h2(a4.z, a4.w);   // (y  , z+1)
    p0.z = pack_h2(b4.x, b4.y);   // (y+1, z  )
    p0.w = pack_h2(b4.z, b4.w);   // (y+1, z+1)

    p1.x = p0.y;                  // (y  , z+1)
    p1.y = pack_h2(c.x, c.y);     // (y  , z+2 clamped)
    p1.z = p0.w;                  // (y+1, z+1)
    p1.w = pack_h2(d.x, d.y);     // (y+1, z+2 clamped)

    g_P2[i]     = p0;
    g_P2[i + 1] = p1;
}

__device__ __forceinline__ float2 h2f(unsigned int u) {
    __half2 h = *(__half2*)&u;
    return __half22float2(h);
}

__device__ __forceinline__ float2 interp_voxel(
    float x, float y, float z, uint4 q0, uint4 q1,
    int x0, int y0u, int z0u, int zc)
{
    // Lower-edge clip duplication (coords >= 0 so ~never taken; keeps exact
    // reference semantics).
    if (z0u < 0) { q0.y = q0.x; q0.w = q0.z; q1.y = q1.x; q1.w = q1.z; }
    if (y0u < 0) { q0.z = q0.x; q0.w = q0.y; q1.z = q1.x; q1.w = q1.y; }

    float2 Ia = h2f(q0.x), Ib = h2f(q0.y), Ic = h2f(q0.z), Id = h2f(q0.w);
    float2 Ie = h2f(q1.x), If = h2f(q1.y), Ig = h2f(q1.z), Ih = h2f(q1.w);

    int y0 = min(max(y0u, 0), YD - 1);
    const float xd = x - (float)x0;
    const float yd = y - (float)y0;
    const float zd = z - (float)zc;
    const float xm = 1.0f - xd;
    const float ym = 1.0f - yd;
    const float zm = 1.0f - zd;

    float cae0 = Ia.x * xm + Ie.x * xd;
    float cae1 = Ia.y * xm + Ie.y * xd;
    float cbf0 = Ib.x * xm + If.x * xd;
    float cbf1 = Ib.y * xm + If.y * xd;
    float ccg0 = Ic.x * xm + Ig.x * xd;
    float ccg1 = Ic.y * xm + Ig.y * xd;
    float cdh0 = Id.x * xm + Ih.x * xd;
    float cdh1 = Id.y * xm + Ih.y * xd;

    float c0_0 = cae0 * ym + ccg0 * yd;
    float c0_1 = cae1 * ym + ccg1 * yd;
    float c1_0 = cbf0 * ym + cdh0 * yd;
    float c1_1 = cbf1 * ym + cdh1 * yd;

    float2 r;
    r.x = c0_0 * zm + c1_0 * zd;
    r.y = c0_1 * zm + c1_1 * zd;
    return r;
}

// Process one voxel-pair given its pre-loaded coords.
__device__ __forceinline__ void do_pair(
    float2 d0, float2 d1, float2 d2,
    float4* __restrict__ out, int gi)
{
    const float xA = d0.x, yA = d0.y, zA = d1.x;
    const float xB = d1.y, yB = d2.x, zB = d2.y;

    int xA0u = (int)floorf(xA), yA0u = (int)floorf(yA), zA0u = (int)floorf(zA);
    int xA0 = min(max(xA0u, 0), XD - 1);
    int xA1 = min(max(xA0u + 1, 0), XD - 1);
    int yA0 = min(max(yA0u, 0), YD - 1);
    int zAc = min(max(zA0u, 0), ZD - 1);

    int xB0u = (int)floorf(xB), yB0u = (int)floorf(yB), zB0u = (int)floorf(zB);
    int xB0 = min(max(xB0u, 0), XD - 1);
    int xB1 = min(max(xB0u + 1, 0), XD - 1);
    int yB0 = min(max(yB0u, 0), YD - 1);
    int zBc = min(max(zB0u, 0), ZD - 1);

    uint4 qA0 = __ldg(&g_P2[(xA0 * YD + yA0) * ZD + zAc]);
    uint4 qA1 = __ldg(&g_P2[(xA1 * YD + yA0) * ZD + zAc]);
    uint4 qB0 = __ldg(&g_P2[(xB0 * YD + yB0) * ZD + zBc]);
    uint4 qB1 = __ldg(&g_P2[(xB1 * YD + yB0) * ZD + zBc]);

    float2 rA = interp_voxel(xA, yA, zA, qA0, qA1, xA0, yA0u, zA0u, zAc);
    float2 rB = interp_voxel(xB, yB, zB, qB0, qB1, xB0, yB0u, zB0u, zBc);

    __stcs(&out[gi / 2], make_float4(rA.x, rA.y, rB.x, rB.y));
}

// ---------- gather: 2 pairs/thread, coords of pair1 prefetched while
// pair0's table gathers are in flight ----------
__global__ __launch_bounds__(THREADS) void gather_kernel(
    const float* __restrict__ defgrid,
    float4* __restrict__ out, int b)
{
    int t = blockIdx.x * THREADS + threadIdx.x;   // 0 .. PSTRIDE-1
    if (t >= PSTRIDE) return;

    int gi0 = b * VOL + 2 * t;                    // pair 0 voxel index
    int gi1 = b * VOL + 2 * (t + PSTRIDE);        // pair 1 voxel index

    const float2* dgA = (const float2*)(defgrid + (size_t)3 * gi0);
    const float2* dgB = (const float2*)(defgrid + (size_t)3 * gi1);

    // coords pair0
    float2 a0 = __ldcs(dgA + 0);
    float2 a1 = __ldcs(dgA + 1);
    float2 a2 = __ldcs(dgA + 2);
    // prefetch coords pair1 (overlaps pair0's gather latency below)
    float2 b0 = __ldcs(dgB + 0);
    float2 b1 = __ldcs(dgB + 1);
    float2 b2 = __ldcs(dgB + 2);

    do_pair(a0, a1, a2, out, gi0);
    do_pair(b0, b1, b2, out, gi1);
}

extern "C" void kernel_launch(void* const* d_in, const int* in_sizes, int n_in,
                              void* d_out, int out_size)
{
    const float2* im     = (const float2*)d_in[0];
    const float* defgrid = (const float*)d_in[1];
    float4* out          = (float4*)d_out;

    for (int b = 0; b < BD; b++) {
        preprocess_kernel<<<PRE_BLOCKS, THREADS>>>(im, b);
        gather_kernel<<<GATHER_BLOCKS, THREADS>>>(defgrid, out, b);
    }
}